// round 14
// baseline (speedup 1.0000x reference)
#include <cuda_runtime.h>
#include <cstdint>
#include <math.h>

#define B_    16384
#define DIN   512
#define DH    1024

// tf32 single-term K dims
#define KS1 1536    // [h | x]
#define KH  1024    // s
#define KHT 1536    // [rh | x]
#define N1  4096

// ---------------- scratch (tf32-rounded fp32) --------------------------------
__device__ float g_A2 [(size_t)B_ * KS1];
__device__ float g_W2 [(size_t)N1 * KS1];
__device__ float g_s  [(size_t)B_ * KH];
__device__ float g_Ws [(size_t)DH * KH];
__device__ float g_Aht[(size_t)B_ * KHT];
__device__ float g_Wht[(size_t)DH * KHT];
__device__ float g_C1 [(size_t)B_ * N1];    // only gates 1 (T) and 3 (z) written
__device__ float g_Tadd[(size_t)B_ * DH];

// ---------------- helpers ----------------------------------------------------
__device__ __forceinline__ uint32_t smem_u32(const void* p) {
    uint32_t a;
    asm("{ .reg .u64 t; cvta.to.shared.u64 t, %1; cvt.u32.u64 %0, t; }" : "=r"(a) : "l"(p));
    return a;
}
__device__ __forceinline__ void cp16(uint32_t sdst, const void* gsrc) {
    asm volatile("cp.async.cg.shared.global [%0], [%1], 16;" :: "r"(sdst), "l"(gsrc));
}
__device__ __forceinline__ void ldsm4(uint32_t* r, uint32_t addr) {
    asm volatile("ldmatrix.sync.aligned.m8n8.x4.shared.b16 {%0,%1,%2,%3}, [%4];"
                 : "=r"(r[0]), "=r"(r[1]), "=r"(r[2]), "=r"(r[3]) : "r"(addr));
}
__device__ __forceinline__ void mma_tf32(float* d, const uint32_t* a, uint32_t b0, uint32_t b1) {
    asm volatile("mma.sync.aligned.m16n8k8.row.col.f32.tf32.tf32.f32 "
                 "{%0,%1,%2,%3}, {%4,%5,%6,%7}, {%8,%9}, {%0,%1,%2,%3};"
                 : "+f"(d[0]), "+f"(d[1]), "+f"(d[2]), "+f"(d[3])
                 : "r"(a[0]), "r"(a[1]), "r"(a[2]), "r"(a[3]), "r"(b0), "r"(b1));
}
__device__ __forceinline__ float to_tf32(float v) {
    uint32_t u;
    asm("cvt.rna.tf32.f32 %0, %1;" : "=r"(u) : "f"(v));
    return __uint_as_float(u);
}
__device__ __forceinline__ float sigm(float x) { return 1.f / (1.f + expf(-x)); }

// ---------------- GEMM core: 128x128 CTA, 128 thr, 4 warps 2Mx2N, BK=32 ------
// warp tile 64x64 (acc[4][8][4]); 3-stage cp.async; 2 CTAs/SM
#define NTHR 128
#define ST_A_BYTES (128 * 128)
#define ST_B_BYTES (128 * 128)
#define ST_STRIDE  (ST_A_BYTES + ST_B_BYTES)   // 32 KB
#define STAGES 3
#define SM_TOT (STAGES * ST_STRIDE)            // 96 KB

__device__ __forceinline__ void load_tile(const float* __restrict__ A,
                                          const float* __restrict__ W,
                                          int K2, int m0, int n0,
                                          uint32_t sbase, int stage, int it, int tid)
{
    const size_t k0 = (size_t)it * 32;               // 32 tf32 per iter
    const uint32_t sA = sbase + stage * ST_STRIDE;
    const uint32_t sB = sA + ST_A_BYTES;
#pragma unroll
    for (int j = 0; j < 16; ++j) {
        int f = tid + j * NTHR;                      // 0..2047
        if (f < 1024) {
            int row = f >> 3, c = f & 7;
            cp16(sA + row * 128 + ((c ^ (row & 7)) << 4),
                 A + (size_t)(m0 + row) * K2 + k0 + c * 4);
        } else {
            int f2 = f - 1024, row = f2 >> 3, c = f2 & 7;
            cp16(sB + row * 128 + ((c ^ (row & 7)) << 4),
                 W + (size_t)(n0 + row) * K2 + k0 + c * 4);
        }
    }
}

__device__ __forceinline__ void gemm_core(const float* __restrict__ A,
                                          const float* __restrict__ W,
                                          int K2, int m0, int n0,
                                          uint32_t sbase, int tid,
                                          float acc[4][8][4])
{
    const int wid = tid >> 5, lane = tid & 31;
    const int wm = (wid & 1) * 64;          // 2 warps in M
    const int wn = (wid >> 1) * 64;         // 2 warps in N
    const int T  = K2 >> 5;

#pragma unroll
    for (int i = 0; i < 4; i++)
#pragma unroll
        for (int j = 0; j < 8; j++)
#pragma unroll
            for (int k = 0; k < 4; k++) acc[i][j][k] = 0.f;

#pragma unroll
    for (int it = 0; it < STAGES - 1; ++it) {
        load_tile(A, W, K2, m0, n0, sbase, it, it, tid);
        asm volatile("cp.async.commit_group;" ::: "memory");
    }

    const int la = lane & 15;
    const int lk = lane >> 4;

    for (int it = 0; it < T; ++it) {
        asm volatile("cp.async.wait_group 1;" ::: "memory");
        __syncthreads();

        int pf = it + STAGES - 1;
        if (pf < T) load_tile(A, W, K2, m0, n0, sbase, pf % STAGES, pf, tid);
        asm volatile("cp.async.commit_group;" ::: "memory");

        const uint32_t aA = sbase + (it % STAGES) * ST_STRIDE;
        const uint32_t aB = aA + ST_A_BYTES;

#pragma unroll
        for (int ks = 0; ks < 4; ++ks) {          // 4 x k8 steps
            const int c = ks * 2 + lk;
            uint32_t af[4][4];
#pragma unroll
            for (int mi = 0; mi < 4; ++mi) {
                int row = wm + mi * 16 + la;
                ldsm4(af[mi], aA + row * 128 + ((c ^ (row & 7)) << 4));
            }
            uint32_t bfr[4][4];
#pragma unroll
            for (int nb = 0; nb < 4; ++nb) {
                int row = wn + nb * 16 + la;
                ldsm4(bfr[nb], aB + row * 128 + ((c ^ (row & 7)) << 4));
            }
#pragma unroll
            for (int mi = 0; mi < 4; ++mi)
#pragma unroll
                for (int nb = 0; nb < 4; ++nb) {
                    mma_tf32(acc[mi][nb * 2 + 0], af[mi], bfr[nb][0], bfr[nb][2]);
                    mma_tf32(acc[mi][nb * 2 + 1], af[mi], bfr[nb][1], bfr[nb][3]);
                }
        }
    }
}

// ---------------- stage-1 GEMM with fused ew1 epilogue ----------------------
// gate = n0>>10: 0 -> s (g_s), 1 -> C1, 2 -> r*h (g_Aht[0:1024]), 3 -> C1
__global__ __launch_bounds__(NTHR, 2)
void gemm_s1_fused(const float* __restrict__ A, const float* __restrict__ W,
                   float* __restrict__ C,
                   const float* __restrict__ delta, const float* __restrict__ Wst,
                   const float* __restrict__ bs, const float* __restrict__ br,
                   const float* __restrict__ h)
{
    extern __shared__ __align__(1024) char smem[];
    const uint32_t sbase = smem_u32(smem);
    const int tid = threadIdx.x;
    const int m0 = blockIdx.y * 128;
    const int n0 = blockIdx.x * 128;

    float acc[4][8][4];
    gemm_core(A, W, KS1, m0, n0, sbase, tid, acc);

    const int wid = tid >> 5, lane = tid & 31;
    const int wm = (wid & 1) * 64;
    const int wn = (wid >> 1) * 64;
    const int gate = n0 >> 10;

#pragma unroll
    for (int mi = 0; mi < 4; ++mi) {
#pragma unroll
        for (int rr = 0; rr < 2; ++rr) {
            const int row = m0 + wm + mi * 16 + (lane >> 2) + rr * 8;
            const float dv = (gate == 0) ? delta[row] : 0.f;
#pragma unroll
            for (int ni = 0; ni < 8; ++ni) {
                const int colg = n0 + wn + ni * 8 + (lane & 3) * 2;
                const int ng   = colg & 1023;
                float v0 = acc[mi][ni][rr * 2 + 0];
                float v1 = acc[mi][ni][rr * 2 + 1];
                if (gate == 0) {
                    float2 sv;
                    sv.x = to_tf32(tanhf(v0 + dv * Wst[ng]     + bs[ng]));
                    sv.y = to_tf32(tanhf(v1 + dv * Wst[ng + 1] + bs[ng + 1]));
                    *(float2*)(g_s + (size_t)row * KH + ng) = sv;
                } else if (gate == 2) {
                    float2 rv;
                    rv.x = to_tf32(sigm(v0 + br[ng])     * h[(size_t)row * DH + ng]);
                    rv.y = to_tf32(sigm(v1 + br[ng + 1]) * h[(size_t)row * DH + ng + 1]);
                    *(float2*)(g_Aht + (size_t)row * KHT + ng) = rv;
                } else {
                    float2 v = { v0, v1 };
                    *(float2*)(C + (size_t)row * N1 + colg) = v;
                }
            }
        }
    }
}

// ---------------- plain GEMM (Tadd) ------------------------------------------
__global__ __launch_bounds__(NTHR, 2)
void gemm_plain(const float* __restrict__ A, const float* __restrict__ W,
                float* __restrict__ C, int K2, int ldc)
{
    extern __shared__ __align__(1024) char smem[];
    const uint32_t sbase = smem_u32(smem);
    const int tid = threadIdx.x;
    const int m0 = blockIdx.y * 128;
    const int n0 = blockIdx.x * 128;

    float acc[4][8][4];
    gemm_core(A, W, K2, m0, n0, sbase, tid, acc);

    const int wid = tid >> 5, lane = tid & 31;
    const int wm = (wid & 1) * 64;
    const int wn = (wid >> 1) * 64;
#pragma unroll
    for (int mi = 0; mi < 4; ++mi) {
        int r0 = m0 + wm + mi * 16 + (lane >> 2);
#pragma unroll
        for (int ni = 0; ni < 8; ++ni) {
            int col = n0 + wn + ni * 8 + (lane & 3) * 2;
            float2 v0 = { acc[mi][ni][0], acc[mi][ni][1] };
            float2 v1 = { acc[mi][ni][2], acc[mi][ni][3] };
            *(float2*)(C + (size_t)r0 * ldc + col)       = v0;
            *(float2*)(C + (size_t)(r0 + 8) * ldc + col) = v1;
        }
    }
}

// ---------------- ht GEMM (rh@W_h^T + x@W_x^T) with fused ew2 epilogue -------
__global__ __launch_bounds__(NTHR, 2)
void gemm_ht_fused(const float* __restrict__ A, const float* __restrict__ W,
                   const float* __restrict__ bT, const float* __restrict__ bz,
                   const float* __restrict__ bb, const float* __restrict__ h,
                   float* __restrict__ out)
{
    extern __shared__ __align__(1024) char smem[];
    const uint32_t sbase = smem_u32(smem);
    const int tid = threadIdx.x;
    const int m0 = blockIdx.y * 128;
    const int n0 = blockIdx.x * 128;

    float acc[4][8][4];
    gemm_core(A, W, KHT, m0, n0, sbase, tid, acc);

    const int wid = tid >> 5, lane = tid & 31;
    const int wm = (wid & 1) * 64;
    const int wn = (wid >> 1) * 64;

#pragma unroll
    for (int mi = 0; mi < 4; ++mi) {
#pragma unroll
        for (int rr = 0; rr < 2; ++rr) {
            const int row = m0 + wm + mi * 16 + (lane >> 2) + rr * 8;
#pragma unroll
            for (int ni = 0; ni < 8; ++ni) {
                const int ng = n0 + wn + ni * 8 + (lane & 3) * 2;
                const size_t e0 = (size_t)row * DH + ng;
                const size_t c0 = (size_t)row * N1 + ng;
                float v0 = acc[mi][ni][rr * 2 + 0];
                float v1 = acc[mi][ni][rr * 2 + 1];
                float T0 = sigm(g_C1[c0 + 1024] + g_Tadd[e0]     + bT[ng]);
                float T1 = sigm(g_C1[c0 + 1025] + g_Tadd[e0 + 1] + bT[ng + 1]);
                float z0 = sigm(g_C1[c0 + 3072] + bz[ng]);
                float z1 = sigm(g_C1[c0 + 3073] + bz[ng + 1]);
                float t0 = tanhf(v0 + bb[ng]);
                float t1 = tanhf(v1 + bb[ng + 1]);
                float2 o;
                o.x = (1.f - z0) * (T0 * h[e0])     + z0 * t0;
                o.y = (1.f - z1) * (T1 * h[e0 + 1]) + z1 * t1;
                *(float2*)(out + e0) = o;
            }
        }
    }
}

// ---------------- conversion kernels (tf32 rounding + concat) ----------------
#define NW2  (N1 * KS1)
#define NWHT (DH * KHT)
#define NWS  (DH * KH)
__global__ void convW_all(const float* __restrict__ Wsh, const float* __restrict__ Wsx,
                          const float* __restrict__ WTh, const float* __restrict__ WTx,
                          const float* __restrict__ Wrh, const float* __restrict__ Wrx,
                          const float* __restrict__ Wzh, const float* __restrict__ Wzx,
                          const float* __restrict__ Wh,  const float* __restrict__ Wx,
                          const float* __restrict__ WTs)
{
    int idx = blockIdx.x * blockDim.x + threadIdx.x;
    if (idx < NW2) {
        int n = idx / KS1, c = idx - n * KS1;
        int blk = n >> 10, r = n & (DH - 1);
        const float* Ph = (blk == 0) ? Wsh : (blk == 1) ? WTh : (blk == 2) ? Wrh : Wzh;
        const float* Px = (blk == 0) ? Wsx : (blk == 1) ? WTx : (blk == 2) ? Wrx : Wzx;
        float v = (c < DH) ? Ph[(size_t)r * DH + c] : Px[(size_t)r * DIN + c - DH];
        g_W2[idx] = to_tf32(v);
        return;
    }
    idx -= NW2;
    if (idx < NWHT) {
        int n = idx / KHT, c = idx - n * KHT;
        float v = (c < DH) ? Wh[(size_t)n * DH + c] : Wx[(size_t)n * DIN + c - DH];
        g_Wht[idx] = to_tf32(v);
        return;
    }
    idx -= NWHT;
    if (idx < NWS) {
        g_Ws[idx] = to_tf32(WTs[idx]);
    }
}
#define NW_ALL (NW2 + NWHT + NWS)

#define NACT (B_ * KS1)
__global__ void convAct(const float* __restrict__ h, const float* __restrict__ x)
{
    int idx = blockIdx.x * blockDim.x + threadIdx.x;
    if (idx >= NACT) return;
    int b = idx / KS1, c = idx - b * KS1;
    if (c < DH) {
        g_A2[idx] = to_tf32(h[(size_t)b * DH + c]);
    } else {
        float xv = to_tf32(x[(size_t)b * DIN + c - DH]);
        g_A2[idx] = xv;
        g_Aht[(size_t)b * KHT + c] = xv;
    }
}

// ---------------- launch ----------------------------------------------------
extern "C" void kernel_launch(void* const* d_in, const int* in_sizes, int n_in,
                              void* d_out, int out_size)
{
    const float* x     = (const float*)d_in[0];
    const float* delta = (const float*)d_in[1];
    const float* h     = (const float*)d_in[2];
    const float* W_sh  = (const float*)d_in[3];
    const float* W_sx  = (const float*)d_in[4];
    const float* W_st  = (const float*)d_in[5];
    const float* b_s   = (const float*)d_in[6];
    const float* WTh   = (const float*)d_in[7];
    const float* WTx   = (const float*)d_in[8];
    const float* WTs   = (const float*)d_in[9];
    const float* b_T   = (const float*)d_in[10];
    const float* W_rh  = (const float*)d_in[11];
    const float* W_rx  = (const float*)d_in[12];
    const float* b_r   = (const float*)d_in[13];
    const float* W_zh  = (const float*)d_in[14];
    const float* W_zx  = (const float*)d_in[15];
    const float* b_z   = (const float*)d_in[16];
    const float* W_h   = (const float*)d_in[17];
    const float* W_x   = (const float*)d_in[18];
    const float* b     = (const float*)d_in[19];
    float* out = (float*)d_out;

    cudaFuncSetAttribute(gemm_s1_fused, cudaFuncAttributeMaxDynamicSharedMemorySize, SM_TOT);
    cudaFuncSetAttribute(gemm_plain,    cudaFuncAttributeMaxDynamicSharedMemorySize, SM_TOT);
    cudaFuncSetAttribute(gemm_ht_fused, cudaFuncAttributeMaxDynamicSharedMemorySize, SM_TOT);

    float *dA2, *dW2, *ds, *dWs, *dAht, *dWht, *dC1, *dTadd;
    cudaGetSymbolAddress((void**)&dA2,   g_A2);
    cudaGetSymbolAddress((void**)&dW2,   g_W2);
    cudaGetSymbolAddress((void**)&ds,    g_s);
    cudaGetSymbolAddress((void**)&dWs,   g_Ws);
    cudaGetSymbolAddress((void**)&dAht,  g_Aht);
    cudaGetSymbolAddress((void**)&dWht,  g_Wht);
    cudaGetSymbolAddress((void**)&dC1,   g_C1);
    cudaGetSymbolAddress((void**)&dTadd, g_Tadd);

    // 1) tf32 rounding + concat
    convW_all<<<(NW_ALL + 255) / 256, 256>>>(W_sh, W_sx, WTh, WTx, W_rh, W_rx,
                                             W_zh, W_zx, W_h, W_x, WTs);
    convAct  <<<(NACT + 255) / 256, 256>>>(h, x);

    // 2) stage-1 GEMM + fused ew1 (K=1536) -> g_s, g_Aht[rh], C1 gates 1&3
    gemm_s1_fused<<<dim3(N1 / 128, B_ / 128), NTHR, SM_TOT>>>(
        dA2, dW2, dC1, delta, W_st, b_s, b_r, h);

    // 3) Tadd = s @ WTs^T  (K=1024)
    gemm_plain<<<dim3(DH / 128, B_ / 128), NTHR, SM_TOT>>>(ds, dWs, dTadd, KH, DH);

    // 4) ht GEMM (rh@W_h^T + x@W_x^T, K=1536) + fused ew2 -> out
    gemm_ht_fused<<<dim3(DH / 128, B_ / 128), NTHR, SM_TOT>>>(
        dAht, dWht, b_T, b_z, b, h, out);
}

// round 15
// speedup vs baseline: 1.1621x; 1.1621x over previous
#include <cuda_runtime.h>
#include <cstdint>
#include <math.h>

#define B_    16384
#define DIN   512
#define DH    1024

// tf32 single-term K dims
#define KS1 1536    // [h | x]
#define KH  1024    // s
#define KHT 1536    // [rh | x]
#define N1  4096

// ---------------- scratch (tf32-rounded fp32) --------------------------------
__device__ float g_A2 [(size_t)B_ * KS1];
__device__ float g_W2 [(size_t)N1 * KS1];
__device__ float g_s  [(size_t)B_ * KH];
__device__ float g_Ws [(size_t)DH * KH];
__device__ float g_Aht[(size_t)B_ * KHT];
__device__ float g_Wht[(size_t)DH * KHT];
__device__ float g_C1 [(size_t)B_ * N1];    // only gates 1 (T) and 3 (z) written
__device__ float g_Tadd[(size_t)B_ * DH];

// ---------------- helpers ----------------------------------------------------
__device__ __forceinline__ uint32_t smem_u32(const void* p) {
    uint32_t a;
    asm("{ .reg .u64 t; cvta.to.shared.u64 t, %1; cvt.u32.u64 %0, t; }" : "=r"(a) : "l"(p));
    return a;
}
__device__ __forceinline__ void cp16(uint32_t sdst, const void* gsrc) {
    asm volatile("cp.async.cg.shared.global [%0], [%1], 16;" :: "r"(sdst), "l"(gsrc));
}
__device__ __forceinline__ void ldsm4(uint32_t* r, uint32_t addr) {
    asm volatile("ldmatrix.sync.aligned.m8n8.x4.shared.b16 {%0,%1,%2,%3}, [%4];"
                 : "=r"(r[0]), "=r"(r[1]), "=r"(r[2]), "=r"(r[3]) : "r"(addr));
}
__device__ __forceinline__ void mma_tf32(float* d, const uint32_t* a, uint32_t b0, uint32_t b1) {
    asm volatile("mma.sync.aligned.m16n8k8.row.col.f32.tf32.tf32.f32 "
                 "{%0,%1,%2,%3}, {%4,%5,%6,%7}, {%8,%9}, {%0,%1,%2,%3};"
                 : "+f"(d[0]), "+f"(d[1]), "+f"(d[2]), "+f"(d[3])
                 : "r"(a[0]), "r"(a[1]), "r"(a[2]), "r"(a[3]), "r"(b0), "r"(b1));
}
__device__ __forceinline__ float to_tf32(float v) {
    uint32_t u;
    asm("cvt.rna.tf32.f32 %0, %1;" : "=r"(u) : "f"(v));
    return __uint_as_float(u);
}
__device__ __forceinline__ float sigm(float x) { return 1.f / (1.f + expf(-x)); }

// ---------------- GEMM core: 128x64 CTA, 256 thr, 8 warps 4Mx2N, BK=32 -------
// warp tile 32x32 (acc[2][4][4]); 3-stage cp.async; 3 CTAs/SM (24 warps)
#define NTHR 256
#define ST_A_BYTES (128 * 128)                 // 16 KB
#define ST_B_BYTES (64 * 128)                  //  8 KB
#define ST_STRIDE  (ST_A_BYTES + ST_B_BYTES)   // 24 KB
#define STAGES 3
#define SM_TOT (STAGES * ST_STRIDE)            // 72 KB

__device__ __forceinline__ void load_tile(const float* __restrict__ A,
                                          const float* __restrict__ W,
                                          int K2, int m0, int n0,
                                          uint32_t sbase, int stage, int it, int tid)
{
    const size_t k0 = (size_t)it * 32;               // 32 tf32 per iter
    const uint32_t sA = sbase + stage * ST_STRIDE;
    const uint32_t sB = sA + ST_A_BYTES;
#pragma unroll
    for (int j = 0; j < 6; ++j) {
        int f = tid + j * NTHR;                      // 0..1535
        if (f < 1024) {
            int row = f >> 3, c = f & 7;
            cp16(sA + row * 128 + ((c ^ (row & 7)) << 4),
                 A + (size_t)(m0 + row) * K2 + k0 + c * 4);
        } else {
            int f2 = f - 1024, row = f2 >> 3, c = f2 & 7;   // row 0..63
            cp16(sB + row * 128 + ((c ^ (row & 7)) << 4),
                 W + (size_t)(n0 + row) * K2 + k0 + c * 4);
        }
    }
}

__device__ __forceinline__ void gemm_core(const float* __restrict__ A,
                                          const float* __restrict__ W,
                                          int K2, int m0, int n0,
                                          uint32_t sbase, int tid,
                                          float acc[2][4][4])
{
    const int wid = tid >> 5, lane = tid & 31;
    const int wm = (wid & 3) * 32;          // 4 warps in M
    const int wn = (wid >> 2) * 32;         // 2 warps in N
    const int T  = K2 >> 5;

#pragma unroll
    for (int i = 0; i < 2; i++)
#pragma unroll
        for (int j = 0; j < 4; j++)
#pragma unroll
            for (int k = 0; k < 4; k++) acc[i][j][k] = 0.f;

#pragma unroll
    for (int it = 0; it < STAGES - 1; ++it) {
        load_tile(A, W, K2, m0, n0, sbase, it, it, tid);
        asm volatile("cp.async.commit_group;" ::: "memory");
    }

    const int la = lane & 15;
    const int lk = lane >> 4;

    for (int it = 0; it < T; ++it) {
        asm volatile("cp.async.wait_group 1;" ::: "memory");
        __syncthreads();

        int pf = it + STAGES - 1;
        if (pf < T) load_tile(A, W, K2, m0, n0, sbase, pf % STAGES, pf, tid);
        asm volatile("cp.async.commit_group;" ::: "memory");

        const uint32_t aA = sbase + (it % STAGES) * ST_STRIDE;
        const uint32_t aB = aA + ST_A_BYTES;

#pragma unroll
        for (int ks = 0; ks < 4; ++ks) {          // 4 x k8 steps
            const int c = ks * 2 + lk;
            uint32_t af[2][4];
#pragma unroll
            for (int mi = 0; mi < 2; ++mi) {
                int row = wm + mi * 16 + la;
                ldsm4(af[mi], aA + row * 128 + ((c ^ (row & 7)) << 4));
            }
            uint32_t bfr[2][4];
#pragma unroll
            for (int nb = 0; nb < 2; ++nb) {
                int row = wn + nb * 16 + la;
                ldsm4(bfr[nb], aB + row * 128 + ((c ^ (row & 7)) << 4));
            }
#pragma unroll
            for (int mi = 0; mi < 2; ++mi)
#pragma unroll
                for (int nb = 0; nb < 2; ++nb) {
                    mma_tf32(acc[mi][nb * 2 + 0], af[mi], bfr[nb][0], bfr[nb][2]);
                    mma_tf32(acc[mi][nb * 2 + 1], af[mi], bfr[nb][1], bfr[nb][3]);
                }
        }
    }
}

// ---------------- stage-1 GEMM with fused ew1 epilogue ----------------------
// gate = n0>>10: 0 -> s (g_s), 1 -> C1, 2 -> r*h (g_Aht[0:1024]), 3 -> C1
__global__ __launch_bounds__(NTHR, 3)
void gemm_s1_fused(const float* __restrict__ A, const float* __restrict__ W,
                   float* __restrict__ C,
                   const float* __restrict__ delta, const float* __restrict__ Wst,
                   const float* __restrict__ bs, const float* __restrict__ br,
                   const float* __restrict__ h)
{
    extern __shared__ __align__(1024) char smem[];
    const uint32_t sbase = smem_u32(smem);
    const int tid = threadIdx.x;
    const int m0 = blockIdx.y * 128;
    const int n0 = blockIdx.x * 64;

    float acc[2][4][4];
    gemm_core(A, W, KS1, m0, n0, sbase, tid, acc);

    const int wid = tid >> 5, lane = tid & 31;
    const int wm = (wid & 3) * 32;
    const int wn = (wid >> 2) * 32;
    const int gate = n0 >> 10;

#pragma unroll
    for (int mi = 0; mi < 2; ++mi) {
#pragma unroll
        for (int rr = 0; rr < 2; ++rr) {
            const int row = m0 + wm + mi * 16 + (lane >> 2) + rr * 8;
            const float dv = (gate == 0) ? delta[row] : 0.f;
#pragma unroll
            for (int ni = 0; ni < 4; ++ni) {
                const int colg = n0 + wn + ni * 8 + (lane & 3) * 2;
                const int ng   = colg & 1023;
                float v0 = acc[mi][ni][rr * 2 + 0];
                float v1 = acc[mi][ni][rr * 2 + 1];
                if (gate == 0) {
                    float2 sv;
                    sv.x = to_tf32(tanhf(v0 + dv * Wst[ng]     + bs[ng]));
                    sv.y = to_tf32(tanhf(v1 + dv * Wst[ng + 1] + bs[ng + 1]));
                    *(float2*)(g_s + (size_t)row * KH + ng) = sv;
                } else if (gate == 2) {
                    float2 rv;
                    rv.x = to_tf32(sigm(v0 + br[ng])     * h[(size_t)row * DH + ng]);
                    rv.y = to_tf32(sigm(v1 + br[ng + 1]) * h[(size_t)row * DH + ng + 1]);
                    *(float2*)(g_Aht + (size_t)row * KHT + ng) = rv;
                } else {
                    float2 v = { v0, v1 };
                    *(float2*)(C + (size_t)row * N1 + colg) = v;
                }
            }
        }
    }
}

// ---------------- plain GEMM (Tadd) ------------------------------------------
__global__ __launch_bounds__(NTHR, 3)
void gemm_plain(const float* __restrict__ A, const float* __restrict__ W,
                float* __restrict__ C, int K2, int ldc)
{
    extern __shared__ __align__(1024) char smem[];
    const uint32_t sbase = smem_u32(smem);
    const int tid = threadIdx.x;
    const int m0 = blockIdx.y * 128;
    const int n0 = blockIdx.x * 64;

    float acc[2][4][4];
    gemm_core(A, W, K2, m0, n0, sbase, tid, acc);

    const int wid = tid >> 5, lane = tid & 31;
    const int wm = (wid & 3) * 32;
    const int wn = (wid >> 2) * 32;
#pragma unroll
    for (int mi = 0; mi < 2; ++mi) {
        int r0 = m0 + wm + mi * 16 + (lane >> 2);
#pragma unroll
        for (int ni = 0; ni < 4; ++ni) {
            int col = n0 + wn + ni * 8 + (lane & 3) * 2;
            float2 v0 = { acc[mi][ni][0], acc[mi][ni][1] };
            float2 v1 = { acc[mi][ni][2], acc[mi][ni][3] };
            *(float2*)(C + (size_t)r0 * ldc + col)       = v0;
            *(float2*)(C + (size_t)(r0 + 8) * ldc + col) = v1;
        }
    }
}

// ---------------- ht GEMM (rh@W_h^T + x@W_x^T) with fused ew2 epilogue -------
__global__ __launch_bounds__(NTHR, 3)
void gemm_ht_fused(const float* __restrict__ A, const float* __restrict__ W,
                   const float* __restrict__ bT, const float* __restrict__ bz,
                   const float* __restrict__ bb, const float* __restrict__ h,
                   float* __restrict__ out)
{
    extern __shared__ __align__(1024) char smem[];
    const uint32_t sbase = smem_u32(smem);
    const int tid = threadIdx.x;
    const int m0 = blockIdx.y * 128;
    const int n0 = blockIdx.x * 64;

    float acc[2][4][4];
    gemm_core(A, W, KHT, m0, n0, sbase, tid, acc);

    const int wid = tid >> 5, lane = tid & 31;
    const int wm = (wid & 3) * 32;
    const int wn = (wid >> 2) * 32;

#pragma unroll
    for (int mi = 0; mi < 2; ++mi) {
#pragma unroll
        for (int rr = 0; rr < 2; ++rr) {
            const int row = m0 + wm + mi * 16 + (lane >> 2) + rr * 8;
#pragma unroll
            for (int ni = 0; ni < 4; ++ni) {
                const int ng = n0 + wn + ni * 8 + (lane & 3) * 2;
                const size_t e0 = (size_t)row * DH + ng;
                const size_t c0 = (size_t)row * N1 + ng;
                float v0 = acc[mi][ni][rr * 2 + 0];
                float v1 = acc[mi][ni][rr * 2 + 1];
                float T0 = sigm(g_C1[c0 + 1024] + g_Tadd[e0]     + bT[ng]);
                float T1 = sigm(g_C1[c0 + 1025] + g_Tadd[e0 + 1] + bT[ng + 1]);
                float z0 = sigm(g_C1[c0 + 3072] + bz[ng]);
                float z1 = sigm(g_C1[c0 + 3073] + bz[ng + 1]);
                float t0 = tanhf(v0 + bb[ng]);
                float t1 = tanhf(v1 + bb[ng + 1]);
                float2 o;
                o.x = (1.f - z0) * (T0 * h[e0])     + z0 * t0;
                o.y = (1.f - z1) * (T1 * h[e0 + 1]) + z1 * t1;
                *(float2*)(out + e0) = o;
            }
        }
    }
}

// ---------------- conversion kernels (tf32 rounding + concat) ----------------
#define NW2  (N1 * KS1)
#define NWHT (DH * KHT)
#define NWS  (DH * KH)
__global__ void convW_all(const float* __restrict__ Wsh, const float* __restrict__ Wsx,
                          const float* __restrict__ WTh, const float* __restrict__ WTx,
                          const float* __restrict__ Wrh, const float* __restrict__ Wrx,
                          const float* __restrict__ Wzh, const float* __restrict__ Wzx,
                          const float* __restrict__ Wh,  const float* __restrict__ Wx,
                          const float* __restrict__ WTs)
{
    int idx = blockIdx.x * blockDim.x + threadIdx.x;
    if (idx < NW2) {
        int n = idx / KS1, c = idx - n * KS1;
        int blk = n >> 10, r = n & (DH - 1);
        const float* Ph = (blk == 0) ? Wsh : (blk == 1) ? WTh : (blk == 2) ? Wrh : Wzh;
        const float* Px = (blk == 0) ? Wsx : (blk == 1) ? WTx : (blk == 2) ? Wrx : Wzx;
        float v = (c < DH) ? Ph[(size_t)r * DH + c] : Px[(size_t)r * DIN + c - DH];
        g_W2[idx] = to_tf32(v);
        return;
    }
    idx -= NW2;
    if (idx < NWHT) {
        int n = idx / KHT, c = idx - n * KHT;
        float v = (c < DH) ? Wh[(size_t)n * DH + c] : Wx[(size_t)n * DIN + c - DH];
        g_Wht[idx] = to_tf32(v);
        return;
    }
    idx -= NWHT;
    if (idx < NWS) {
        g_Ws[idx] = to_tf32(WTs[idx]);
    }
}
#define NW_ALL (NW2 + NWHT + NWS)

#define NACT (B_ * KS1)
__global__ void convAct(const float* __restrict__ h, const float* __restrict__ x)
{
    int idx = blockIdx.x * blockDim.x + threadIdx.x;
    if (idx >= NACT) return;
    int b = idx / KS1, c = idx - b * KS1;
    if (c < DH) {
        g_A2[idx] = to_tf32(h[(size_t)b * DH + c]);
    } else {
        float xv = to_tf32(x[(size_t)b * DIN + c - DH]);
        g_A2[idx] = xv;
        g_Aht[(size_t)b * KHT + c] = xv;
    }
}

// ---------------- launch ----------------------------------------------------
extern "C" void kernel_launch(void* const* d_in, const int* in_sizes, int n_in,
                              void* d_out, int out_size)
{
    const float* x     = (const float*)d_in[0];
    const float* delta = (const float*)d_in[1];
    const float* h     = (const float*)d_in[2];
    const float* W_sh  = (const float*)d_in[3];
    const float* W_sx  = (const float*)d_in[4];
    const float* W_st  = (const float*)d_in[5];
    const float* b_s   = (const float*)d_in[6];
    const float* WTh   = (const float*)d_in[7];
    const float* WTx   = (const float*)d_in[8];
    const float* WTs   = (const float*)d_in[9];
    const float* b_T   = (const float*)d_in[10];
    const float* W_rh  = (const float*)d_in[11];
    const float* W_rx  = (const float*)d_in[12];
    const float* b_r   = (const float*)d_in[13];
    const float* W_zh  = (const float*)d_in[14];
    const float* W_zx  = (const float*)d_in[15];
    const float* b_z   = (const float*)d_in[16];
    const float* W_h   = (const float*)d_in[17];
    const float* W_x   = (const float*)d_in[18];
    const float* b     = (const float*)d_in[19];
    float* out = (float*)d_out;

    cudaFuncSetAttribute(gemm_s1_fused, cudaFuncAttributeMaxDynamicSharedMemorySize, SM_TOT);
    cudaFuncSetAttribute(gemm_plain,    cudaFuncAttributeMaxDynamicSharedMemorySize, SM_TOT);
    cudaFuncSetAttribute(gemm_ht_fused, cudaFuncAttributeMaxDynamicSharedMemorySize, SM_TOT);

    float *dA2, *dW2, *ds, *dWs, *dAht, *dWht, *dC1, *dTadd;
    cudaGetSymbolAddress((void**)&dA2,   g_A2);
    cudaGetSymbolAddress((void**)&dW2,   g_W2);
    cudaGetSymbolAddress((void**)&ds,    g_s);
    cudaGetSymbolAddress((void**)&dWs,   g_Ws);
    cudaGetSymbolAddress((void**)&dAht,  g_Aht);
    cudaGetSymbolAddress((void**)&dWht,  g_Wht);
    cudaGetSymbolAddress((void**)&dC1,   g_C1);
    cudaGetSymbolAddress((void**)&dTadd, g_Tadd);

    // 1) tf32 rounding + concat
    convW_all<<<(NW_ALL + 255) / 256, 256>>>(W_sh, W_sx, WTh, WTx, W_rh, W_rx,
                                             W_zh, W_zx, W_h, W_x, WTs);
    convAct  <<<(NACT + 255) / 256, 256>>>(h, x);

    // 2) stage-1 GEMM + fused ew1 (K=1536) -> g_s, g_Aht[rh], C1 gates 1&3
    gemm_s1_fused<<<dim3(N1 / 64, B_ / 128), NTHR, SM_TOT>>>(
        dA2, dW2, dC1, delta, W_st, b_s, b_r, h);

    // 3) Tadd = s @ WTs^T  (K=1024)
    gemm_plain<<<dim3(DH / 64, B_ / 128), NTHR, SM_TOT>>>(ds, dWs, dTadd, KH, DH);

    // 4) ht GEMM (rh@W_h^T + x@W_x^T, K=1536) + fused ew2 -> out
    gemm_ht_fused<<<dim3(DH / 64, B_ / 128), NTHR, SM_TOT>>>(
        dAht, dWht, b_T, b_z, b, h, out);
}

// round 16
// speedup vs baseline: 1.2135x; 1.0442x over previous
#include <cuda_runtime.h>
#include <cstdint>
#include <math.h>

#define B_    16384
#define DIN   512
#define DH    1024

// tf32 single-term K dims
#define KS1 1536    // [h | x]
#define KH  1024    // s
#define KHT 1536    // [rh | A2-x slice]
#define N1  4096

// ---------------- scratch (tf32-rounded fp32) --------------------------------
__device__ float g_A2 [(size_t)B_ * KS1];   // [h | x]
__device__ float g_W2 [(size_t)N1 * KS1];
__device__ float g_s  [(size_t)B_ * KH];
__device__ float g_Ws [(size_t)DH * KH];
__device__ float g_rh [(size_t)B_ * KH];    // r_t * h (dense 1024)
__device__ float g_Wht[(size_t)DH * KHT];   // [W_h | W_x]
__device__ float g_gT [(size_t)B_ * DH];    // T pre-act (dense)
__device__ float g_gz [(size_t)B_ * DH];    // z pre-act (dense)
__device__ float g_Tadd[(size_t)B_ * DH];

// ---------------- helpers ----------------------------------------------------
__device__ __forceinline__ uint32_t smem_u32(const void* p) {
    uint32_t a;
    asm("{ .reg .u64 t; cvta.to.shared.u64 t, %1; cvt.u32.u64 %0, t; }" : "=r"(a) : "l"(p));
    return a;
}
__device__ __forceinline__ void cp16(uint32_t sdst, const void* gsrc) {
    asm volatile("cp.async.cg.shared.global [%0], [%1], 16;" :: "r"(sdst), "l"(gsrc));
}
__device__ __forceinline__ void ldsm4(uint32_t* r, uint32_t addr) {
    asm volatile("ldmatrix.sync.aligned.m8n8.x4.shared.b16 {%0,%1,%2,%3}, [%4];"
                 : "=r"(r[0]), "=r"(r[1]), "=r"(r[2]), "=r"(r[3]) : "r"(addr));
}
__device__ __forceinline__ void mma_tf32(float* d, const uint32_t* a, uint32_t b0, uint32_t b1) {
    asm volatile("mma.sync.aligned.m16n8k8.row.col.f32.tf32.tf32.f32 "
                 "{%0,%1,%2,%3}, {%4,%5,%6,%7}, {%8,%9}, {%0,%1,%2,%3};"
                 : "+f"(d[0]), "+f"(d[1]), "+f"(d[2]), "+f"(d[3])
                 : "r"(a[0]), "r"(a[1]), "r"(a[2]), "r"(a[3]), "r"(b0), "r"(b1));
}
__device__ __forceinline__ float to_tf32(float v) {
    uint32_t u;
    asm("cvt.rna.tf32.f32 %0, %1;" : "=r"(u) : "f"(v));
    return __uint_as_float(u);
}
__device__ __forceinline__ float sigm(float x) { return 1.f / (1.f + expf(-x)); }

// ---------------- GEMM core (R9 config): 128x128 CTA, 256 thr, 8 warps 4Mx2N -
// warp tile 32x64, BK=32 tf32 (128B rows), 3-stage cp.async, 2 CTAs/SM
#define NTHR 256
#define ST_A_BYTES (128 * 128)
#define ST_B_BYTES (128 * 128)
#define ST_STRIDE  (ST_A_BYTES + ST_B_BYTES)   // 32 KB
#define STAGES 3
#define SM_TOT (STAGES * ST_STRIDE)            // 96 KB

// single-source tile loader (A stride = K2)
__device__ __forceinline__ void load_tile(const float* __restrict__ A,
                                          const float* __restrict__ W,
                                          int K2, int m0, int n0,
                                          uint32_t sbase, int stage, int it, int tid)
{
    const size_t k0 = (size_t)it * 32;
    const uint32_t sA = sbase + stage * ST_STRIDE;
    const uint32_t sB = sA + ST_A_BYTES;
#pragma unroll
    for (int j = 0; j < 8; ++j) {
        int f = tid + j * NTHR;                      // 0..2047
        if (f < 1024) {
            int row = f >> 3, c = f & 7;
            cp16(sA + row * 128 + ((c ^ (row & 7)) << 4),
                 A + (size_t)(m0 + row) * K2 + k0 + c * 4);
        } else {
            int f2 = f - 1024, row = f2 >> 3, c = f2 & 7;
            cp16(sB + row * 128 + ((c ^ (row & 7)) << 4),
                 W + (size_t)(n0 + row) * K2 + k0 + c * 4);
        }
    }
}

// dual-source loader for ht GEMM: k<1024 -> rh (stride 1024), k>=1024 -> A2 x-slice (stride 1536)
__device__ __forceinline__ void load_tile_ht(const float* __restrict__ Arh,
                                             const float* __restrict__ A2,
                                             const float* __restrict__ W,
                                             int m0, int n0,
                                             uint32_t sbase, int stage, int it, int tid)
{
    const size_t k0 = (size_t)it * 32;
    const uint32_t sA = sbase + stage * ST_STRIDE;
    const uint32_t sB = sA + ST_A_BYTES;
    const bool xpart = (k0 >= 1024);
#pragma unroll
    for (int j = 0; j < 8; ++j) {
        int f = tid + j * NTHR;
        if (f < 1024) {
            int row = f >> 3, c = f & 7;
            const float* src = xpart
                ? (A2  + (size_t)(m0 + row) * KS1 + k0 + c * 4)   // cols 1024..1535 of A2 = x
                : (Arh + (size_t)(m0 + row) * KH  + k0 + c * 4);
            cp16(sA + row * 128 + ((c ^ (row & 7)) << 4), src);
        } else {
            int f2 = f - 1024, row = f2 >> 3, c = f2 & 7;
            cp16(sB + row * 128 + ((c ^ (row & 7)) << 4),
                 W + (size_t)(n0 + row) * KHT + k0 + c * 4);
        }
    }
}

// macro-expanded core body so both loaders share the pipeline structure
#define GEMM_PIPE(LOADER_CALL_PROLOG, LOADER_CALL_STEADY, T)                     \
    do {                                                                          \
        _Pragma("unroll")                                                         \
        for (int it = 0; it < STAGES - 1; ++it) {                                 \
            LOADER_CALL_PROLOG;                                                   \
            asm volatile("cp.async.commit_group;" ::: "memory");                  \
        }                                                                         \
        const int la = lane & 15;                                                 \
        const int lk = lane >> 4;                                                 \
        for (int it = 0; it < (T); ++it) {                                        \
            asm volatile("cp.async.wait_group 1;" ::: "memory");                  \
            __syncthreads();                                                      \
            int pf = it + STAGES - 1;                                             \
            if (pf < (T)) { LOADER_CALL_STEADY; }                                 \
            asm volatile("cp.async.commit_group;" ::: "memory");                  \
            const uint32_t aA = sbase + (it % STAGES) * ST_STRIDE;                \
            const uint32_t aB = aA + ST_A_BYTES;                                  \
            _Pragma("unroll")                                                     \
            for (int ks = 0; ks < 4; ++ks) {                                      \
                const int c = ks * 2 + lk;                                        \
                uint32_t af[2][4];                                                \
                _Pragma("unroll")                                                 \
                for (int mi = 0; mi < 2; ++mi) {                                  \
                    int row = wm + mi * 16 + la;                                  \
                    ldsm4(af[mi], aA + row * 128 + ((c ^ (row & 7)) << 4));       \
                }                                                                 \
                uint32_t bfr[4][4];                                               \
                _Pragma("unroll")                                                 \
                for (int nb = 0; nb < 4; ++nb) {                                  \
                    int row = wn + nb * 16 + la;                                  \
                    ldsm4(bfr[nb], aB + row * 128 + ((c ^ (row & 7)) << 4));      \
                }                                                                 \
                _Pragma("unroll")                                                 \
                for (int mi = 0; mi < 2; ++mi)                                    \
                    _Pragma("unroll")                                             \
                    for (int nb = 0; nb < 4; ++nb) {                              \
                        mma_tf32(acc[mi][nb * 2 + 0], af[mi], bfr[nb][0], bfr[nb][2]); \
                        mma_tf32(acc[mi][nb * 2 + 1], af[mi], bfr[nb][1], bfr[nb][3]); \
                    }                                                             \
            }                                                                     \
        }                                                                         \
    } while (0)

// ---------------- stage-1 GEMM with fused ew1 epilogue ----------------------
// gate = n0>>10: 0 -> s (g_s), 1 -> gT, 2 -> r*h (g_rh), 3 -> gz
__global__ __launch_bounds__(NTHR, 2)
void gemm_s1_fused(const float* __restrict__ A, const float* __restrict__ W,
                   const float* __restrict__ delta, const float* __restrict__ Wst,
                   const float* __restrict__ bs, const float* __restrict__ br,
                   const float* __restrict__ h)
{
    extern __shared__ __align__(1024) char smem[];
    const uint32_t sbase = smem_u32(smem);
    const int tid = threadIdx.x;
    const int m0 = blockIdx.y * 128;
    const int n0 = blockIdx.x * 128;
    const int wid = tid >> 5, lane = tid & 31;
    const int wm = (wid & 3) * 32;
    const int wn = (wid >> 2) * 64;

    float acc[2][8][4];
#pragma unroll
    for (int i = 0; i < 2; i++)
#pragma unroll
        for (int j = 0; j < 8; j++)
#pragma unroll
            for (int k = 0; k < 4; k++) acc[i][j][k] = 0.f;

    GEMM_PIPE(load_tile(A, W, KS1, m0, n0, sbase, it, it, tid),
              load_tile(A, W, KS1, m0, n0, sbase, pf % STAGES, pf, tid),
              (KS1 >> 5));

    const int gate = n0 >> 10;
#pragma unroll
    for (int mi = 0; mi < 2; ++mi) {
#pragma unroll
        for (int rr = 0; rr < 2; ++rr) {
            const int row = m0 + wm + mi * 16 + (lane >> 2) + rr * 8;
            const float dv = (gate == 0) ? delta[row] : 0.f;
#pragma unroll
            for (int ni = 0; ni < 8; ++ni) {
                const int colg = n0 + wn + ni * 8 + (lane & 3) * 2;
                const int ng   = colg & 1023;
                float v0 = acc[mi][ni][rr * 2 + 0];
                float v1 = acc[mi][ni][rr * 2 + 1];
                const size_t e0 = (size_t)row * DH + ng;
                if (gate == 0) {
                    float2 sv;
                    sv.x = to_tf32(tanhf(v0 + dv * Wst[ng]     + bs[ng]));
                    sv.y = to_tf32(tanhf(v1 + dv * Wst[ng + 1] + bs[ng + 1]));
                    *(float2*)(g_s + e0) = sv;
                } else if (gate == 2) {
                    float2 rv;
                    rv.x = to_tf32(sigm(v0 + br[ng])     * h[e0]);
                    rv.y = to_tf32(sigm(v1 + br[ng + 1]) * h[e0 + 1]);
                    *(float2*)(g_rh + e0) = rv;
                } else if (gate == 1) {
                    float2 v = { v0, v1 };
                    *(float2*)(g_gT + e0) = v;
                } else {
                    float2 v = { v0, v1 };
                    *(float2*)(g_gz + e0) = v;
                }
            }
        }
    }
}

// ---------------- plain GEMM (Tadd = s @ WTs^T) ------------------------------
__global__ __launch_bounds__(NTHR, 2)
void gemm_plain(const float* __restrict__ A, const float* __restrict__ W,
                float* __restrict__ C, int K2, int ldc)
{
    extern __shared__ __align__(1024) char smem[];
    const uint32_t sbase = smem_u32(smem);
    const int tid = threadIdx.x;
    const int m0 = blockIdx.y * 128;
    const int n0 = blockIdx.x * 128;
    const int wid = tid >> 5, lane = tid & 31;
    const int wm = (wid & 3) * 32;
    const int wn = (wid >> 2) * 64;

    float acc[2][8][4];
#pragma unroll
    for (int i = 0; i < 2; i++)
#pragma unroll
        for (int j = 0; j < 8; j++)
#pragma unroll
            for (int k = 0; k < 4; k++) acc[i][j][k] = 0.f;

    GEMM_PIPE(load_tile(A, W, K2, m0, n0, sbase, it, it, tid),
              load_tile(A, W, K2, m0, n0, sbase, pf % STAGES, pf, tid),
              (K2 >> 5));

#pragma unroll
    for (int mi = 0; mi < 2; ++mi) {
        int r0 = m0 + wm + mi * 16 + (lane >> 2);
#pragma unroll
        for (int ni = 0; ni < 8; ++ni) {
            int col = n0 + wn + ni * 8 + (lane & 3) * 2;
            float2 v0 = { acc[mi][ni][0], acc[mi][ni][1] };
            float2 v1 = { acc[mi][ni][2], acc[mi][ni][3] };
            *(float2*)(C + (size_t)r0 * ldc + col)       = v0;
            *(float2*)(C + (size_t)(r0 + 8) * ldc + col) = v1;
        }
    }
}

// ---------------- ht GEMM (dual-source A) with fused ew2 epilogue ------------
__global__ __launch_bounds__(NTHR, 2)
void gemm_ht_fused(const float* __restrict__ Arh, const float* __restrict__ A2,
                   const float* __restrict__ W,
                   const float* __restrict__ bT, const float* __restrict__ bz,
                   const float* __restrict__ bb, const float* __restrict__ h,
                   float* __restrict__ out)
{
    extern __shared__ __align__(1024) char smem[];
    const uint32_t sbase = smem_u32(smem);
    const int tid = threadIdx.x;
    const int m0 = blockIdx.y * 128;
    const int n0 = blockIdx.x * 128;
    const int wid = tid >> 5, lane = tid & 31;
    const int wm = (wid & 3) * 32;
    const int wn = (wid >> 2) * 64;

    float acc[2][8][4];
#pragma unroll
    for (int i = 0; i < 2; i++)
#pragma unroll
        for (int j = 0; j < 8; j++)
#pragma unroll
            for (int k = 0; k < 4; k++) acc[i][j][k] = 0.f;

    GEMM_PIPE(load_tile_ht(Arh, A2, W, m0, n0, sbase, it, it, tid),
              load_tile_ht(Arh, A2, W, m0, n0, sbase, pf % STAGES, pf, tid),
              (KHT >> 5));

#pragma unroll
    for (int mi = 0; mi < 2; ++mi) {
#pragma unroll
        for (int rr = 0; rr < 2; ++rr) {
            const int row = m0 + wm + mi * 16 + (lane >> 2) + rr * 8;
#pragma unroll
            for (int ni = 0; ni < 8; ++ni) {
                const int ng = n0 + wn + ni * 8 + (lane & 3) * 2;
                const size_t e0 = (size_t)row * DH + ng;
                float v0 = acc[mi][ni][rr * 2 + 0];
                float v1 = acc[mi][ni][rr * 2 + 1];
                float T0 = sigm(g_gT[e0]     + g_Tadd[e0]     + bT[ng]);
                float T1 = sigm(g_gT[e0 + 1] + g_Tadd[e0 + 1] + bT[ng + 1]);
                float z0 = sigm(g_gz[e0]     + bz[ng]);
                float z1 = sigm(g_gz[e0 + 1] + bz[ng + 1]);
                float t0 = tanhf(v0 + bb[ng]);
                float t1 = tanhf(v1 + bb[ng + 1]);
                float2 o;
                o.x = (1.f - z0) * (T0 * h[e0])     + z0 * t0;
                o.y = (1.f - z1) * (T1 * h[e0 + 1]) + z1 * t1;
                *(float2*)(out + e0) = o;
            }
        }
    }
}

// ---------------- single fused conversion kernel -----------------------------
#define NW2  (N1 * KS1)
#define NWHT (DH * KHT)
#define NWS  (DH * KH)
#define NACT (B_ * KS1)
#define NTOT (NW2 + NWHT + NWS + NACT)
__global__ void convAll(const float* __restrict__ Wsh, const float* __restrict__ Wsx,
                        const float* __restrict__ WTh, const float* __restrict__ WTx,
                        const float* __restrict__ Wrh, const float* __restrict__ Wrx,
                        const float* __restrict__ Wzh, const float* __restrict__ Wzx,
                        const float* __restrict__ Wh,  const float* __restrict__ Wx,
                        const float* __restrict__ WTs,
                        const float* __restrict__ hin, const float* __restrict__ xin)
{
    int idx = blockIdx.x * blockDim.x + threadIdx.x;
    if (idx < NW2) {
        int n = idx / KS1, c = idx - n * KS1;
        int blk = n >> 10, r = n & (DH - 1);
        const float* Ph = (blk == 0) ? Wsh : (blk == 1) ? WTh : (blk == 2) ? Wrh : Wzh;
        const float* Px = (blk == 0) ? Wsx : (blk == 1) ? WTx : (blk == 2) ? Wrx : Wzx;
        float v = (c < DH) ? Ph[(size_t)r * DH + c] : Px[(size_t)r * DIN + c - DH];
        g_W2[idx] = to_tf32(v);
        return;
    }
    idx -= NW2;
    if (idx < NWHT) {
        int n = idx / KHT, c = idx - n * KHT;
        float v = (c < DH) ? Wh[(size_t)n * DH + c] : Wx[(size_t)n * DIN + c - DH];
        g_Wht[idx] = to_tf32(v);
        return;
    }
    idx -= NWHT;
    if (idx < NWS) {
        g_Ws[idx] = to_tf32(WTs[idx]);
        return;
    }
    idx -= NWS;
    if (idx < NACT) {
        int b = idx / KS1, c = idx - b * KS1;
        float v = (c < DH) ? hin[(size_t)b * DH + c] : xin[(size_t)b * DIN + c - DH];
        g_A2[idx] = to_tf32(v);
    }
}

// ---------------- launch ----------------------------------------------------
extern "C" void kernel_launch(void* const* d_in, const int* in_sizes, int n_in,
                              void* d_out, int out_size)
{
    const float* x     = (const float*)d_in[0];
    const float* delta = (const float*)d_in[1];
    const float* h     = (const float*)d_in[2];
    const float* W_sh  = (const float*)d_in[3];
    const float* W_sx  = (const float*)d_in[4];
    const float* W_st  = (const float*)d_in[5];
    const float* b_s   = (const float*)d_in[6];
    const float* WTh   = (const float*)d_in[7];
    const float* WTx   = (const float*)d_in[8];
    const float* WTs   = (const float*)d_in[9];
    const float* b_T   = (const float*)d_in[10];
    const float* W_rh  = (const float*)d_in[11];
    const float* W_rx  = (const float*)d_in[12];
    const float* b_r   = (const float*)d_in[13];
    const float* W_zh  = (const float*)d_in[14];
    const float* W_zx  = (const float*)d_in[15];
    const float* b_z   = (const float*)d_in[16];
    const float* W_h   = (const float*)d_in[17];
    const float* W_x   = (const float*)d_in[18];
    const float* b     = (const float*)d_in[19];
    float* out = (float*)d_out;

    cudaFuncSetAttribute(gemm_s1_fused, cudaFuncAttributeMaxDynamicSharedMemorySize, SM_TOT);
    cudaFuncSetAttribute(gemm_plain,    cudaFuncAttributeMaxDynamicSharedMemorySize, SM_TOT);
    cudaFuncSetAttribute(gemm_ht_fused, cudaFuncAttributeMaxDynamicSharedMemorySize, SM_TOT);

    float *dA2, *dW2, *ds, *dWs, *drh, *dWht, *dTadd;
    cudaGetSymbolAddress((void**)&dA2,   g_A2);
    cudaGetSymbolAddress((void**)&dW2,   g_W2);
    cudaGetSymbolAddress((void**)&ds,    g_s);
    cudaGetSymbolAddress((void**)&dWs,   g_Ws);
    cudaGetSymbolAddress((void**)&drh,   g_rh);
    cudaGetSymbolAddress((void**)&dWht,  g_Wht);
    cudaGetSymbolAddress((void**)&dTadd, g_Tadd);

    // 1) tf32 rounding + concat (one launch)
    convAll<<<(NTOT + 255) / 256, 256>>>(W_sh, W_sx, WTh, WTx, W_rh, W_rx,
                                         W_zh, W_zx, W_h, W_x, WTs, h, x);

    // 2) stage-1 GEMM + fused ew1 (K=1536) -> g_s, g_rh, gT, gz
    gemm_s1_fused<<<dim3(N1 / 128, B_ / 128), NTHR, SM_TOT>>>(
        dA2, dW2, delta, W_st, b_s, b_r, h);

    // 3) Tadd = s @ WTs^T  (K=1024)
    gemm_plain<<<dim3(DH / 128, B_ / 128), NTHR, SM_TOT>>>(ds, dWs, dTadd, KH, DH);

    // 4) ht GEMM (rh@W_h^T + x@W_x^T via dual-source A, K=1536) + fused ew2 -> out
    gemm_ht_fused<<<dim3(DH / 128, B_ / 128), NTHR, SM_TOT>>>(
        drh, dA2, dWht, b_T, b_z, b, h, out);
}

// round 17
// speedup vs baseline: 1.2201x; 1.0055x over previous
#include <cuda_runtime.h>
#include <cstdint>
#include <math.h>

#define B_    16384
#define DIN   512
#define DH    1024

// tf32 single-term K dims
#define KS1 1536    // [h | x]
#define KH  1024    // s
#define KHT 1536    // [rh | x]
#define N1  4096

// ---------------- scratch (tf32-rounded fp32) --------------------------------
__device__ float g_A2 [(size_t)B_ * KS1];   // [h | x]
__device__ float g_W2 [(size_t)N1 * KS1];
__device__ float g_s  [(size_t)B_ * KH];
__device__ float g_Ws [(size_t)DH * KH];
__device__ float g_Aht[(size_t)B_ * KHT];   // [rh | x]
__device__ float g_Wht[(size_t)DH * KHT];   // [W_h | W_x]
__device__ float g_gT [(size_t)B_ * DH];    // T pre-act (dense)
__device__ float g_gz [(size_t)B_ * DH];    // z pre-act (dense)
__device__ float g_Tadd[(size_t)B_ * DH];

// ---------------- helpers ----------------------------------------------------
__device__ __forceinline__ uint32_t smem_u32(const void* p) {
    uint32_t a;
    asm("{ .reg .u64 t; cvta.to.shared.u64 t, %1; cvt.u32.u64 %0, t; }" : "=r"(a) : "l"(p));
    return a;
}
__device__ __forceinline__ void cp16(uint32_t sdst, const void* gsrc) {
    asm volatile("cp.async.cg.shared.global [%0], [%1], 16;" :: "r"(sdst), "l"(gsrc));
}
__device__ __forceinline__ void ldsm4(uint32_t* r, uint32_t addr) {
    asm volatile("ldmatrix.sync.aligned.m8n8.x4.shared.b16 {%0,%1,%2,%3}, [%4];"
                 : "=r"(r[0]), "=r"(r[1]), "=r"(r[2]), "=r"(r[3]) : "r"(addr));
}
__device__ __forceinline__ void mma_tf32(float* d, const uint32_t* a, uint32_t b0, uint32_t b1) {
    asm volatile("mma.sync.aligned.m16n8k8.row.col.f32.tf32.tf32.f32 "
                 "{%0,%1,%2,%3}, {%4,%5,%6,%7}, {%8,%9}, {%0,%1,%2,%3};"
                 : "+f"(d[0]), "+f"(d[1]), "+f"(d[2]), "+f"(d[3])
                 : "r"(a[0]), "r"(a[1]), "r"(a[2]), "r"(a[3]), "r"(b0), "r"(b1));
}
__device__ __forceinline__ float to_tf32(float v) {
    uint32_t u;
    asm("cvt.rna.tf32.f32 %0, %1;" : "=r"(u) : "f"(v));
    return __uint_as_float(u);
}
__device__ __forceinline__ float sigm(float x) { return 1.f / (1.f + expf(-x)); }

// ---------------- GEMM core (R9 config): 128x128 CTA, 256 thr, 8 warps 4Mx2N -
// warp tile 32x64, BK=32 tf32 (128B rows), 3-stage cp.async, 2 CTAs/SM
#define NTHR 256
#define ST_A_BYTES (128 * 128)
#define ST_B_BYTES (128 * 128)
#define ST_STRIDE  (ST_A_BYTES + ST_B_BYTES)   // 32 KB
#define STAGES 3
#define SM_TOT (STAGES * ST_STRIDE)            // 96 KB

__device__ __forceinline__ void load_tile(const float* __restrict__ A,
                                          const float* __restrict__ W,
                                          int KA, int KB, int m0, int n0,
                                          uint32_t sbase, int stage, int it, int tid)
{
    const size_t k0 = (size_t)it * 32;
    const uint32_t sA = sbase + stage * ST_STRIDE;
    const uint32_t sB = sA + ST_A_BYTES;
#pragma unroll
    for (int j = 0; j < 8; ++j) {
        int f = tid + j * NTHR;                      // 0..2047
        if (f < 1024) {
            int row = f >> 3, c = f & 7;
            cp16(sA + row * 128 + ((c ^ (row & 7)) << 4),
                 A + (size_t)(m0 + row) * KA + k0 + c * 4);
        } else {
            int f2 = f - 1024, row = f2 >> 3, c = f2 & 7;
            cp16(sB + row * 128 + ((c ^ (row & 7)) << 4),
                 W + (size_t)(n0 + row) * KB + k0 + c * 4);
        }
    }
}

// shared pipeline body
#define GEMM_PIPE(KA, KB, T)                                                     \
    do {                                                                          \
        _Pragma("unroll")                                                         \
        for (int it = 0; it < STAGES - 1; ++it) {                                 \
            load_tile(A, W, KA, KB, m0, n0, sbase, it, it, tid);                  \
            asm volatile("cp.async.commit_group;" ::: "memory");                  \
        }                                                                         \
        const int la = lane & 15;                                                 \
        const int lk = lane >> 4;                                                 \
        for (int it = 0; it < (T); ++it) {                                        \
            asm volatile("cp.async.wait_group 1;" ::: "memory");                  \
            __syncthreads();                                                      \
            int pf = it + STAGES - 1;                                             \
            if (pf < (T)) load_tile(A, W, KA, KB, m0, n0, sbase, pf % STAGES, pf, tid); \
            asm volatile("cp.async.commit_group;" ::: "memory");                  \
            const uint32_t aA = sbase + (it % STAGES) * ST_STRIDE;                \
            const uint32_t aB = aA + ST_A_BYTES;                                  \
            _Pragma("unroll")                                                     \
            for (int ks = 0; ks < 4; ++ks) {                                      \
                const int c = ks * 2 + lk;                                        \
                uint32_t af[2][4];                                                \
                _Pragma("unroll")                                                 \
                for (int mi = 0; mi < 2; ++mi) {                                  \
                    int row = wm + mi * 16 + la;                                  \
                    ldsm4(af[mi], aA + row * 128 + ((c ^ (row & 7)) << 4));       \
                }                                                                 \
                uint32_t bfr[4][4];                                               \
                _Pragma("unroll")                                                 \
                for (int nb = 0; nb < 4; ++nb) {                                  \
                    int row = wn + nb * 16 + la;                                  \
                    ldsm4(bfr[nb], aB + row * 128 + ((c ^ (row & 7)) << 4));      \
                }                                                                 \
                _Pragma("unroll")                                                 \
                for (int mi = 0; mi < 2; ++mi)                                    \
                    _Pragma("unroll")                                             \
                    for (int nb = 0; nb < 4; ++nb) {                              \
                        mma_tf32(acc[mi][nb * 2 + 0], af[mi], bfr[nb][0], bfr[nb][2]); \
                        mma_tf32(acc[mi][nb * 2 + 1], af[mi], bfr[nb][1], bfr[nb][3]); \
                    }                                                             \
            }                                                                     \
        }                                                                         \
    } while (0)

// ---------------- stage-1 GEMM with fused ew1 epilogue ----------------------
// gate = n0>>10: 0 -> s (g_s), 1 -> gT, 2 -> r*h (g_Aht[:,0:1024]), 3 -> gz
__global__ __launch_bounds__(NTHR, 2)
void gemm_s1_fused(const float* __restrict__ A, const float* __restrict__ W,
                   const float* __restrict__ delta, const float* __restrict__ Wst,
                   const float* __restrict__ bs, const float* __restrict__ br,
                   const float* __restrict__ h)
{
    extern __shared__ __align__(1024) char smem[];
    const uint32_t sbase = smem_u32(smem);
    const int tid = threadIdx.x;
    const int m0 = blockIdx.y * 128;
    const int n0 = blockIdx.x * 128;
    const int wid = tid >> 5, lane = tid & 31;
    const int wm = (wid & 3) * 32;
    const int wn = (wid >> 2) * 64;

    float acc[2][8][4];
#pragma unroll
    for (int i = 0; i < 2; i++)
#pragma unroll
        for (int j = 0; j < 8; j++)
#pragma unroll
            for (int k = 0; k < 4; k++) acc[i][j][k] = 0.f;

    GEMM_PIPE(KS1, KS1, (KS1 >> 5));

    const int gate = n0 >> 10;
#pragma unroll
    for (int mi = 0; mi < 2; ++mi) {
#pragma unroll
        for (int rr = 0; rr < 2; ++rr) {
            const int row = m0 + wm + mi * 16 + (lane >> 2) + rr * 8;
            const float dv = (gate == 0) ? delta[row] : 0.f;
#pragma unroll
            for (int ni = 0; ni < 8; ++ni) {
                const int colg = n0 + wn + ni * 8 + (lane & 3) * 2;
                const int ng   = colg & 1023;
                float v0 = acc[mi][ni][rr * 2 + 0];
                float v1 = acc[mi][ni][rr * 2 + 1];
                const size_t e0 = (size_t)row * DH + ng;
                if (gate == 0) {
                    float2 sv;
                    sv.x = to_tf32(tanhf(v0 + dv * Wst[ng]     + bs[ng]));
                    sv.y = to_tf32(tanhf(v1 + dv * Wst[ng + 1] + bs[ng + 1]));
                    *(float2*)(g_s + e0) = sv;
                } else if (gate == 2) {
                    float2 rv;
                    rv.x = to_tf32(sigm(v0 + br[ng])     * h[e0]);
                    rv.y = to_tf32(sigm(v1 + br[ng + 1]) * h[e0 + 1]);
                    *(float2*)(g_Aht + (size_t)row * KHT + ng) = rv;
                } else if (gate == 1) {
                    float2 v = { v0, v1 };
                    *(float2*)(g_gT + e0) = v;
                } else {
                    float2 v = { v0, v1 };
                    *(float2*)(g_gz + e0) = v;
                }
            }
        }
    }
}

// ---------------- plain GEMM (Tadd = s @ WTs^T) ------------------------------
__global__ __launch_bounds__(NTHR, 2)
void gemm_plain(const float* __restrict__ A, const float* __restrict__ W,
                float* __restrict__ C, int K2, int ldc)
{
    extern __shared__ __align__(1024) char smem[];
    const uint32_t sbase = smem_u32(smem);
    const int tid = threadIdx.x;
    const int m0 = blockIdx.y * 128;
    const int n0 = blockIdx.x * 128;
    const int wid = tid >> 5, lane = tid & 31;
    const int wm = (wid & 3) * 32;
    const int wn = (wid >> 2) * 64;

    float acc[2][8][4];
#pragma unroll
    for (int i = 0; i < 2; i++)
#pragma unroll
        for (int j = 0; j < 8; j++)
#pragma unroll
            for (int k = 0; k < 4; k++) acc[i][j][k] = 0.f;

    GEMM_PIPE(K2, K2, (K2 >> 5));

#pragma unroll
    for (int mi = 0; mi < 2; ++mi) {
        int r0 = m0 + wm + mi * 16 + (lane >> 2);
#pragma unroll
        for (int ni = 0; ni < 8; ++ni) {
            int col = n0 + wn + ni * 8 + (lane & 3) * 2;
            float2 v0 = { acc[mi][ni][0], acc[mi][ni][1] };
            float2 v1 = { acc[mi][ni][2], acc[mi][ni][3] };
            *(float2*)(C + (size_t)r0 * ldc + col)       = v0;
            *(float2*)(C + (size_t)(r0 + 8) * ldc + col) = v1;
        }
    }
}

// ---------------- ht GEMM (Aht @ Wht^T, K=1536) with fused ew2 epilogue ------
__global__ __launch_bounds__(NTHR, 2)
void gemm_ht_fused(const float* __restrict__ A, const float* __restrict__ W,
                   const float* __restrict__ bT, const float* __restrict__ bz,
                   const float* __restrict__ bb, const float* __restrict__ h,
                   float* __restrict__ out)
{
    extern __shared__ __align__(1024) char smem[];
    const uint32_t sbase = smem_u32(smem);
    const int tid = threadIdx.x;
    const int m0 = blockIdx.y * 128;
    const int n0 = blockIdx.x * 128;
    const int wid = tid >> 5, lane = tid & 31;
    const int wm = (wid & 3) * 32;
    const int wn = (wid >> 2) * 64;

    float acc[2][8][4];
#pragma unroll
    for (int i = 0; i < 2; i++)
#pragma unroll
        for (int j = 0; j < 8; j++)
#pragma unroll
            for (int k = 0; k < 4; k++) acc[i][j][k] = 0.f;

    GEMM_PIPE(KHT, KHT, (KHT >> 5));

#pragma unroll
    for (int mi = 0; mi < 2; ++mi) {
#pragma unroll
        for (int rr = 0; rr < 2; ++rr) {
            const int row = m0 + wm + mi * 16 + (lane >> 2) + rr * 8;
#pragma unroll
            for (int ni = 0; ni < 8; ++ni) {
                const int ng = n0 + wn + ni * 8 + (lane & 3) * 2;
                const size_t e0 = (size_t)row * DH + ng;
                float v0 = acc[mi][ni][rr * 2 + 0];
                float v1 = acc[mi][ni][rr * 2 + 1];
                float T0 = sigm(g_gT[e0]     + g_Tadd[e0]     + bT[ng]);
                float T1 = sigm(g_gT[e0 + 1] + g_Tadd[e0 + 1] + bT[ng + 1]);
                float z0 = sigm(g_gz[e0]     + bz[ng]);
                float z1 = sigm(g_gz[e0 + 1] + bz[ng + 1]);
                float t0 = tanhf(v0 + bb[ng]);
                float t1 = tanhf(v1 + bb[ng + 1]);
                float2 o;
                o.x = (1.f - z0) * (T0 * h[e0])     + z0 * t0;
                o.y = (1.f - z1) * (T1 * h[e0 + 1]) + z1 * t1;
                *(float2*)(out + e0) = o;
            }
        }
    }
}

// ---------------- single fused conversion kernel -----------------------------
#define NW2  (N1 * KS1)
#define NWHT (DH * KHT)
#define NWS  (DH * KH)
#define NACT (B_ * KS1)
#define NTOT (NW2 + NWHT + NWS + NACT)
__global__ void convAll(const float* __restrict__ Wsh, const float* __restrict__ Wsx,
                        const float* __restrict__ WTh, const float* __restrict__ WTx,
                        const float* __restrict__ Wrh, const float* __restrict__ Wrx,
                        const float* __restrict__ Wzh, const float* __restrict__ Wzx,
                        const float* __restrict__ Wh,  const float* __restrict__ Wx,
                        const float* __restrict__ WTs,
                        const float* __restrict__ hin, const float* __restrict__ xin)
{
    int idx = blockIdx.x * blockDim.x + threadIdx.x;
    if (idx < NW2) {
        int n = idx / KS1, c = idx - n * KS1;
        int blk = n >> 10, r = n & (DH - 1);
        const float* Ph = (blk == 0) ? Wsh : (blk == 1) ? WTh : (blk == 2) ? Wrh : Wzh;
        const float* Px = (blk == 0) ? Wsx : (blk == 1) ? WTx : (blk == 2) ? Wrx : Wzx;
        float v = (c < DH) ? Ph[(size_t)r * DH + c] : Px[(size_t)r * DIN + c - DH];
        g_W2[idx] = to_tf32(v);
        return;
    }
    idx -= NW2;
    if (idx < NWHT) {
        int n = idx / KHT, c = idx - n * KHT;
        float v = (c < DH) ? Wh[(size_t)n * DH + c] : Wx[(size_t)n * DIN + c - DH];
        g_Wht[idx] = to_tf32(v);
        return;
    }
    idx -= NWHT;
    if (idx < NWS) {
        g_Ws[idx] = to_tf32(WTs[idx]);
        return;
    }
    idx -= NWS;
    if (idx < NACT) {
        int b = idx / KS1, c = idx - b * KS1;
        if (c < DH) {
            g_A2[idx] = to_tf32(hin[(size_t)b * DH + c]);
        } else {
            float xv = to_tf32(xin[(size_t)b * DIN + c - DH]);
            g_A2[idx] = xv;
            g_Aht[(size_t)b * KHT + c] = xv;   // x slice of ht operand
        }
    }
}

// ---------------- launch ----------------------------------------------------
extern "C" void kernel_launch(void* const* d_in, const int* in_sizes, int n_in,
                              void* d_out, int out_size)
{
    const float* x     = (const float*)d_in[0];
    const float* delta = (const float*)d_in[1];
    const float* h     = (const float*)d_in[2];
    const float* W_sh  = (const float*)d_in[3];
    const float* W_sx  = (const float*)d_in[4];
    const float* W_st  = (const float*)d_in[5];
    const float* b_s   = (const float*)d_in[6];
    const float* WTh   = (const float*)d_in[7];
    const float* WTx   = (const float*)d_in[8];
    const float* WTs   = (const float*)d_in[9];
    const float* b_T   = (const float*)d_in[10];
    const float* W_rh  = (const float*)d_in[11];
    const float* W_rx  = (const float*)d_in[12];
    const float* b_r   = (const float*)d_in[13];
    const float* W_zh  = (const float*)d_in[14];
    const float* W_zx  = (const float*)d_in[15];
    const float* b_z   = (const float*)d_in[16];
    const float* W_h   = (const float*)d_in[17];
    const float* W_x   = (const float*)d_in[18];
    const float* b     = (const float*)d_in[19];
    float* out = (float*)d_out;

    cudaFuncSetAttribute(gemm_s1_fused, cudaFuncAttributeMaxDynamicSharedMemorySize, SM_TOT);
    cudaFuncSetAttribute(gemm_plain,    cudaFuncAttributeMaxDynamicSharedMemorySize, SM_TOT);
    cudaFuncSetAttribute(gemm_ht_fused, cudaFuncAttributeMaxDynamicSharedMemorySize, SM_TOT);

    float *dA2, *dW2, *ds, *dWs, *dAht, *dWht, *dTadd;
    cudaGetSymbolAddress((void**)&dA2,   g_A2);
    cudaGetSymbolAddress((void**)&dW2,   g_W2);
    cudaGetSymbolAddress((void**)&ds,    g_s);
    cudaGetSymbolAddress((void**)&dWs,   g_Ws);
    cudaGetSymbolAddress((void**)&dAht,  g_Aht);
    cudaGetSymbolAddress((void**)&dWht,  g_Wht);
    cudaGetSymbolAddress((void**)&dTadd, g_Tadd);

    // 1) tf32 rounding + concat (one launch)
    convAll<<<(NTOT + 255) / 256, 256>>>(W_sh, W_sx, WTh, WTx, W_rh, W_rx,
                                         W_zh, W_zx, W_h, W_x, WTs, h, x);

    // 2) stage-1 GEMM + fused ew1 (K=1536) -> g_s, g_Aht[rh], gT, gz
    gemm_s1_fused<<<dim3(N1 / 128, B_ / 128), NTHR, SM_TOT>>>(
        dA2, dW2, delta, W_st, b_s, b_r, h);

    // 3) Tadd = s @ WTs^T  (K=1024)
    gemm_plain<<<dim3(DH / 128, B_ / 128), NTHR, SM_TOT>>>(ds, dWs, dTadd, KH, DH);

    // 4) ht GEMM (Aht @ Wht^T, K=1536) + fused ew2 -> out
    gemm_ht_fused<<<dim3(DH / 128, B_ / 128), NTHR, SM_TOT>>>(
        dAht, dWht, b_T, b_z, b, h, out);
}